// round 1
// baseline (speedup 1.0000x reference)
#include <cuda_runtime.h>
#include <math.h>

#define BATCH 8
#define CH    1792
#define HW    3136
#define WCOLS 1794

// ---------------- scratch (device globals; no allocation APIs) ----------------
__device__ float g_y1[BATCH * CH * 3136];   // level-1 GEMM out  (b, o, 56*56)
__device__ float g_p1[BATCH * CH * 3136];   // pooled
__device__ float g_y2[BATCH * CH * 784];    // level-2 GEMM out  (b, o, 28*28)
__device__ float g_p2[BATCH * CH * 784];
__device__ float g_y3[BATCH * CH * 196];    // level-3 GEMM out  (b, o, 14*14)
__device__ float g_p3[BATCH * CH * 196];
__device__ float g_phi[BATCH * CH * 3136];  // assembled phi (b, o, 56*56)
__device__ float g_rown[BATCH * HW];        // ||phi_i||^2
__device__ float g_coln[HW];                // ||C_j||^2
__device__ float g_top3[BATCH * 3 * HW * 3];// partial top-3 d^2 per j-split

__device__ __forceinline__ void ins3(float &a0, float &a1, float &a2, float x)
{
    // keep 3 smallest, sorted ascending
    float o0 = fminf(a0, x);
    float o1 = fminf(a1, fmaxf(a0, x));
    float o2 = fminf(a2, fmaxf(a1, x));
    a0 = o0; a1 = o1; a2 = o2;
}

// ============================================================================
// Level GEMM: Y[b][o][s] = sum_c W[o, woff+c] * X[b][c][s]
// A = W (row-major, lda=1794), B = X (k-major, n contiguous)
// BM=128, BN=128, BK=16, 256 threads, 8x8 per thread
// ============================================================================
__global__ __launch_bounds__(256, 2)
void level_gemm(const float* __restrict__ Wmat, const float* __restrict__ X,
                float* __restrict__ Y, int K, int Nloc, int woff)
{
    const int b  = blockIdx.z;
    const int m0 = blockIdx.y * 128;
    const int n0 = blockIdx.x * 128;
    const float* Xb = X + (size_t)b * K * Nloc;
    float*       Yb = Y + (size_t)b * CH * Nloc;

    __shared__ __align__(16) float As[16][132];  // pad to reduce STS conflicts
    __shared__ __align__(16) float Bs[16][128];

    const int tid = threadIdx.x;
    const int tx = tid & 15;
    const int ty = tid >> 4;

    float acc[8][8];
#pragma unroll
    for (int i = 0; i < 8; i++)
#pragma unroll
        for (int j = 0; j < 8; j++) acc[i][j] = 0.f;

    for (int k0 = 0; k0 < K; k0 += 16) {
        // A tile: 128 m x 16 k, scalar loads (stride 1794 breaks vector align),
        // stored transposed As[k][m]
        {
            const int ka = tid & 15;
            const int ma = tid >> 4;
#pragma unroll
            for (int p = 0; p < 8; p++) {
                int m = ma + p * 16;
                As[ka][m] = Wmat[(size_t)(m0 + m) * WCOLS + woff + k0 + ka];
            }
        }
        // B tile: 16 k x 128 n, float4 (Nloc % 4 == 0 for 3136/784/196)
        {
            const int kb = tid >> 5;
            const int nb = (tid & 31) * 4;
#pragma unroll
            for (int p = 0; p < 2; p++) {
                int k = kb + p * 8;
                float4 v = make_float4(0.f, 0.f, 0.f, 0.f);
                int n = n0 + nb;
                if (n < Nloc)
                    v = *reinterpret_cast<const float4*>(&Xb[(size_t)(k0 + k) * Nloc + n]);
                *reinterpret_cast<float4*>(&Bs[k][nb]) = v;
            }
        }
        __syncthreads();
#pragma unroll
        for (int kk = 0; kk < 16; kk++) {
            float a[8], bb[8];
            float4 av0 = *reinterpret_cast<const float4*>(&As[kk][ty * 8]);
            float4 av1 = *reinterpret_cast<const float4*>(&As[kk][ty * 8 + 4]);
            float4 bv0 = *reinterpret_cast<const float4*>(&Bs[kk][tx * 8]);
            float4 bv1 = *reinterpret_cast<const float4*>(&Bs[kk][tx * 8 + 4]);
            a[0]=av0.x; a[1]=av0.y; a[2]=av0.z; a[3]=av0.w;
            a[4]=av1.x; a[5]=av1.y; a[6]=av1.z; a[7]=av1.w;
            bb[0]=bv0.x; bb[1]=bv0.y; bb[2]=bv0.z; bb[3]=bv0.w;
            bb[4]=bv1.x; bb[5]=bv1.y; bb[6]=bv1.z; bb[7]=bv1.w;
#pragma unroll
            for (int i = 0; i < 8; i++)
#pragma unroll
                for (int j = 0; j < 8; j++)
                    acc[i][j] = fmaf(a[i], bb[j], acc[i][j]);
        }
        __syncthreads();
    }

#pragma unroll
    for (int i = 0; i < 8; i++) {
        int m = m0 + ty * 8 + i;
#pragma unroll
        for (int j = 0; j < 8; j += 4) {
            int n = n0 + tx * 8 + j;
            if (n < Nloc) {
                float4 v = make_float4(acc[i][j], acc[i][j+1], acc[i][j+2], acc[i][j+3]);
                *reinterpret_cast<float4*>(&Yb[(size_t)m * Nloc + n]) = v;
            }
        }
    }
}

// ============================================================================
// 3x3 avg pool, stride 1, zero pad, /9 (count_include_pad)
// ============================================================================
__global__ void pool3(const float* __restrict__ in, float* __restrict__ out,
                      int S, int total)
{
    int idx = blockIdx.x * blockDim.x + threadIdx.x;
    if (idx >= total) return;
    int w = idx % S;
    int h = (idx / S) % S;
    int plane = idx / (S * S);
    const float* ip = in + (size_t)plane * S * S;
    float s = 0.f;
#pragma unroll
    for (int dh = -1; dh <= 1; dh++) {
        int hh = h + dh;
        if (hh < 0 || hh >= S) continue;
#pragma unroll
        for (int dw = -1; dw <= 1; dw++) {
            int ww = w + dw;
            if (ww < 0 || ww >= S) continue;
            s += ip[hh * S + ww];
        }
    }
    out[idx] = s * (1.f / 9.f);
}

// half-pixel bilinear sample of SxS plane at 56x56 output coord (h, w)
__device__ __forceinline__ float bilin(const float* __restrict__ p, int S, int h, int w)
{
    float scale = (float)S / 56.f;
    float cy = (h + 0.5f) * scale - 0.5f;
    float cx = (w + 0.5f) * scale - 0.5f;
    float fy0 = floorf(cy), fx0 = floorf(cx);
    float fy = cy - fy0, fx = cx - fx0;
    int y0 = (int)fy0, x0 = (int)fx0;
    int y0c = max(y0, 0), y1c = min(y0 + 1, S - 1);
    int x0c = max(x0, 0), x1c = min(x0 + 1, S - 1);
    float v00 = p[y0c * S + x0c], v01 = p[y0c * S + x1c];
    float v10 = p[y1c * S + x0c], v11 = p[y1c * S + x1c];
    return (1.f - fy) * ((1.f - fx) * v00 + fx * v01)
         +        fy  * ((1.f - fx) * v10 + fx * v11);
}

// ============================================================================
// phi = P1 + up2(P2) + up4(P3) + W[:,1792]*xx + W[:,1793]*yy + b
// ============================================================================
__global__ void assemble(const float* __restrict__ Wmat, const float* __restrict__ bvec)
{
    int idx = blockIdx.x * blockDim.x + threadIdx.x;
    if (idx >= BATCH * CH * HW) return;
    int w = idx % 56;
    int h = (idx / 56) % 56;
    int o = (idx / HW) % CH;
    int b = idx / (HW * CH);

    float v = g_p1[idx];
    const float* p2 = g_p2 + ((size_t)(b * CH) + o) * 784;
    const float* p3 = g_p3 + ((size_t)(b * CH) + o) * 196;
    v += bilin(p2, 28, h, w);
    v += bilin(p3, 14, h, w);
    float xx = fmaf(2.f / 55.f, (float)w, -1.f);
    float yy = fmaf(2.f / 55.f, (float)h, -1.f);
    v += Wmat[(size_t)o * WCOLS + 1792] * xx
       + Wmat[(size_t)o * WCOLS + 1793] * yy
       + bvec[o];
    g_phi[idx] = v;
}

__global__ void row_norms()
{
    int i = blockIdx.x * blockDim.x + threadIdx.x;
    int b = blockIdx.y;
    if (i >= HW) return;
    const float* p = g_phi + (size_t)b * CH * HW + i;
    float s = 0.f;
#pragma unroll 4
    for (int k = 0; k < CH; k++) {
        float v = p[(size_t)k * HW];
        s = fmaf(v, v, s);
    }
    g_rown[b * HW + i] = s;
}

__global__ void col_norms(const float* __restrict__ Cmat)
{
    int j = blockIdx.x * blockDim.x + threadIdx.x;
    if (j >= HW) return;
    float s = 0.f;
#pragma unroll 4
    for (int k = 0; k < CH; k++) {
        float v = Cmat[(size_t)k * HW + j];
        s = fmaf(v, v, s);
    }
    g_coln[j] = s;
}

// ============================================================================
// Fused distance GEMM + running top-3 (of dist^2).
// A[k][i] = phi[b][k][i] (k-major), B[k][j] = C[k][j] (k-major)
// grid: (i-tiles=25, batch=8, j-split=3); block 256 thr, 128x128 tile, 8x8/thr
// ============================================================================
__global__ __launch_bounds__(256, 2)
void dist_topk(const float* __restrict__ Cmat)
{
    const int m0 = blockIdx.x * 128;
    const int b  = blockIdx.y;
    const int js = blockIdx.z;
    const int jt0 = (js * 25) / 3;
    const int jt1 = ((js + 1) * 25) / 3;

    __shared__ __align__(16) float As[16][128];
    __shared__ __align__(16) float Bs[16][128];

    const int tid = threadIdx.x;
    const int tx = tid & 15;
    const int ty = tid >> 4;

    const float* Pb = g_phi + (size_t)b * CH * HW;

    float t0[8], t1[8], t2[8], ni[8];
#pragma unroll
    for (int i = 0; i < 8; i++) {
        t0[i] = INFINITY; t1[i] = INFINITY; t2[i] = INFINITY;
        int ig = m0 + ty * 8 + i;
        ni[i] = (ig < HW) ? g_rown[b * HW + ig] : 0.f;
    }

    for (int jt = jt0; jt < jt1; jt++) {
        const int n0 = jt * 128;
        float acc[8][8];
#pragma unroll
        for (int i = 0; i < 8; i++)
#pragma unroll
            for (int j = 0; j < 8; j++) acc[i][j] = 0.f;

        for (int k0 = 0; k0 < CH; k0 += 16) {
            const int kb = tid >> 5;
            const int c4 = (tid & 31) * 4;
#pragma unroll
            for (int p = 0; p < 2; p++) {
                int k = kb + p * 8;
                float4 va = make_float4(0.f, 0.f, 0.f, 0.f);
                if (m0 + c4 < HW)
                    va = *reinterpret_cast<const float4*>(&Pb[(size_t)(k0 + k) * HW + m0 + c4]);
                *reinterpret_cast<float4*>(&As[k][c4]) = va;
                float4 vb = make_float4(0.f, 0.f, 0.f, 0.f);
                if (n0 + c4 < HW)
                    vb = *reinterpret_cast<const float4*>(&Cmat[(size_t)(k0 + k) * HW + n0 + c4]);
                *reinterpret_cast<float4*>(&Bs[k][c4]) = vb;
            }
            __syncthreads();
#pragma unroll
            for (int kk = 0; kk < 16; kk++) {
                float a[8], bb[8];
                float4 av0 = *reinterpret_cast<const float4*>(&As[kk][ty * 8]);
                float4 av1 = *reinterpret_cast<const float4*>(&As[kk][ty * 8 + 4]);
                float4 bv0 = *reinterpret_cast<const float4*>(&Bs[kk][tx * 8]);
                float4 bv1 = *reinterpret_cast<const float4*>(&Bs[kk][tx * 8 + 4]);
                a[0]=av0.x; a[1]=av0.y; a[2]=av0.z; a[3]=av0.w;
                a[4]=av1.x; a[5]=av1.y; a[6]=av1.z; a[7]=av1.w;
                bb[0]=bv0.x; bb[1]=bv0.y; bb[2]=bv0.z; bb[3]=bv0.w;
                bb[4]=bv1.x; bb[5]=bv1.y; bb[6]=bv1.z; bb[7]=bv1.w;
#pragma unroll
                for (int i = 0; i < 8; i++)
#pragma unroll
                    for (int j = 0; j < 8; j++)
                        acc[i][j] = fmaf(a[i], bb[j], acc[i][j]);
            }
            __syncthreads();
        }

        // epilogue: dist^2 and insert into running top-3
#pragma unroll
        for (int j = 0; j < 8; j++) {
            int jg = n0 + tx * 8 + j;
            bool jv = (jg < HW);
            float mj = jv ? g_coln[jg] : 0.f;
#pragma unroll
            for (int i = 0; i < 8; i++) {
                float d2 = jv ? fmaf(-2.f, acc[i][j], ni[i] + mj) : INFINITY;
                ins3(t0[i], t1[i], t2[i], d2);
            }
        }
    }

    // merge across the 16 tx-threads of each row (they share ty; lanes form a
    // contiguous half-warp so xor masks 1,2,4,8 stay within the group)
#pragma unroll
    for (int msk = 1; msk < 16; msk <<= 1) {
#pragma unroll
        for (int i = 0; i < 8; i++) {
            float b0 = __shfl_xor_sync(0xffffffffu, t0[i], msk);
            float b1 = __shfl_xor_sync(0xffffffffu, t1[i], msk);
            float b2 = __shfl_xor_sync(0xffffffffu, t2[i], msk);
            ins3(t0[i], t1[i], t2[i], b0);
            ins3(t0[i], t1[i], t2[i], b1);
            ins3(t0[i], t1[i], t2[i], b2);
        }
    }

    if (tx == 0) {
#pragma unroll
        for (int i = 0; i < 8; i++) {
            int ig = m0 + ty * 8 + i;
            if (ig < HW) {
                size_t base = (((size_t)b * 3 + js) * HW + ig) * 3;
                g_top3[base + 0] = t0[i];
                g_top3[base + 1] = t1[i];
                g_top3[base + 2] = t2[i];
            }
        }
    }
}

// ============================================================================
// merge j-split partials, sqrt, softmin, score
// ============================================================================
__global__ void finalize(float* __restrict__ out)
{
    int idx = blockIdx.x * blockDim.x + threadIdx.x;
    if (idx >= BATCH * HW) return;
    int b = idx / HW;
    int i = idx % HW;
    float t0 = INFINITY, t1 = INFINITY, t2 = INFINITY;
#pragma unroll
    for (int js = 0; js < 3; js++) {
        size_t base = (((size_t)b * 3 + js) * HW + i) * 3;
        ins3(t0, t1, t2, g_top3[base + 0]);
        ins3(t0, t1, t2, g_top3[base + 1]);
        ins3(t0, t1, t2, g_top3[base + 2]);
    }
    float d0 = sqrtf(fmaxf(t0, 0.f));
    float d1 = sqrtf(fmaxf(t1, 0.f));
    float d2 = sqrtf(fmaxf(t2, 0.f));
    // softmin weight of smallest: stable since d0 <= d1 <= d2
    float w0 = 1.f / (1.f + expf(d0 - d1) + expf(d0 - d2));
    out[idx] = w0 * d0;
}

// ============================================================================
extern "C" void kernel_launch(void* const* d_in, const int* in_sizes, int n_in,
                              void* d_out, int out_size)
{
    const float *p1 = nullptr, *p2 = nullptr, *p3 = nullptr;
    const float *W = nullptr, *bv = nullptr, *Cm = nullptr;
    for (int i = 0; i < n_in; i++) {
        switch (in_sizes[i]) {
            case 8 * 256 * 56 * 56:  p1 = (const float*)d_in[i]; break;  // 6422528
            case 8 * 512 * 28 * 28:  p2 = (const float*)d_in[i]; break;  // 3211264
            case 8 * 1024 * 14 * 14: p3 = (const float*)d_in[i]; break;  // 1605632
            case 1792 * 1794:        W  = (const float*)d_in[i]; break;  // 3214848
            case 1792:               bv = (const float*)d_in[i]; break;
            case 1792 * 3136:        Cm = (const float*)d_in[i]; break;  // 5619712
            default: break;
        }
    }

    void *y1, *pp1, *y2, *pp2, *y3, *pp3;
    cudaGetSymbolAddress(&y1,  g_y1);
    cudaGetSymbolAddress(&pp1, g_p1);
    cudaGetSymbolAddress(&y2,  g_y2);
    cudaGetSymbolAddress(&pp2, g_p2);
    cudaGetSymbolAddress(&y3,  g_y3);
    cudaGetSymbolAddress(&pp3, g_p3);

    // channel-mix at native resolution (commutes with pool/upsample)
    level_gemm<<<dim3(25, 14, 8), 256>>>(W, p1, (float*)y1, 256, 3136, 0);
    level_gemm<<<dim3(7, 14, 8), 256>>>(W, p2, (float*)y2, 512, 784, 256);
    level_gemm<<<dim3(2, 14, 8), 256>>>(W, p3, (float*)y3, 1024, 196, 768);

    const int tot1 = BATCH * CH * 3136;
    const int tot2 = BATCH * CH * 784;
    const int tot3 = BATCH * CH * 196;
    pool3<<<(tot1 + 255) / 256, 256>>>((const float*)y1, (float*)pp1, 56, tot1);
    pool3<<<(tot2 + 255) / 256, 256>>>((const float*)y2, (float*)pp2, 28, tot2);
    pool3<<<(tot3 + 255) / 256, 256>>>((const float*)y3, (float*)pp3, 14, tot3);

    assemble<<<(tot1 + 255) / 256, 256>>>(W, bv);

    row_norms<<<dim3((HW + 255) / 256, BATCH), 256>>>();
    col_norms<<<(HW + 255) / 256, 256>>>(Cm);

    dist_topk<<<dim3(25, BATCH, 3), 256>>>(Cm);

    finalize<<<(BATCH * HW + 255) / 256, 256>>>((float*)d_out);
}

// round 2
// speedup vs baseline: 3.2060x; 3.2060x over previous
#include <cuda_runtime.h>
#include <cuda_bf16.h>
#include <math.h>
#include <stdint.h>

#define BATCH 8
#define CH    1792
#define HW    3136
#define WCOLS 1794

// ---------------- scratch (device globals; no allocation APIs) ----------------
__device__ float g_y1[BATCH * CH * 3136];   // level-1 GEMM out  (b, o, 56*56)
__device__ float g_p1[BATCH * CH * 3136];   // pooled
__device__ float g_y2[BATCH * CH * 784];
__device__ float g_p2[BATCH * CH * 784];
__device__ float g_y3[BATCH * CH * 196];
__device__ float g_p3[BATCH * CH * 196];
__device__ float g_phi[BATCH * CH * 3136];  // assembled phi fp32 (b, k, i)
__device__ float g_rown[BATCH * HW];        // ||phi_i||^2
__device__ float g_coln[HW];                // ||C_j||^2
__device__ float g_top3[BATCH * 3 * HW * 3];// partial top-3 d^2 per j-split

// bf16 staging (row-major [row][k] for mma)
__device__ __nv_bfloat16 g_Wb [CH * CH];                 // W[o][c] bf16
__device__ __nv_bfloat16 g_x1t[BATCH * 3136 * 256];      // (b, s, c)
__device__ __nv_bfloat16 g_x2t[BATCH * 784  * 512];
__device__ __nv_bfloat16 g_x3t[BATCH * 196  * 1024];
__device__ __nv_bfloat16 g_Ct [HW * CH];                 // (j, k)
__device__ __nv_bfloat16 g_phiT[BATCH * HW * CH];        // (b, i, k)

__device__ __forceinline__ void ins3(float &a0, float &a1, float &a2, float x)
{
    float o0 = fminf(a0, x);
    float o1 = fminf(a1, fmaxf(a0, x));
    float o2 = fminf(a2, fmaxf(a1, x));
    a0 = o0; a1 = o1; a2 = o2;
}

__device__ __forceinline__ uint32_t smem_u32(const void* p)
{
    uint32_t a;
    asm("{ .reg .u64 t; cvta.to.shared.u64 t, %1; cvt.u32.u64 %0, t; }"
        : "=r"(a) : "l"(p));
    return a;
}

__device__ __forceinline__ void ldsm4(uint32_t &r0, uint32_t &r1, uint32_t &r2,
                                      uint32_t &r3, uint32_t addr)
{
    asm volatile("ldmatrix.sync.aligned.m8n8.x4.shared.b16 {%0,%1,%2,%3}, [%4];"
                 : "=r"(r0), "=r"(r1), "=r"(r2), "=r"(r3) : "r"(addr));
}

__device__ __forceinline__ void mma16816(float c[4],
                                         uint32_t a0, uint32_t a1, uint32_t a2, uint32_t a3,
                                         uint32_t b0, uint32_t b1)
{
    asm volatile("mma.sync.aligned.m16n8k16.row.col.f32.bf16.bf16.f32 "
                 "{%0,%1,%2,%3}, {%4,%5,%6,%7}, {%8,%9}, {%0,%1,%2,%3};"
                 : "+f"(c[0]), "+f"(c[1]), "+f"(c[2]), "+f"(c[3])
                 : "r"(a0), "r"(a1), "r"(a2), "r"(a3), "r"(b0), "r"(b1));
}

// ============================================================================
// fp32 (P, R, S) -> bf16 (P, S, R) tiled transpose+convert
// ============================================================================
__global__ void transpose_conv(const float* __restrict__ in,
                               __nv_bfloat16* __restrict__ out, int R, int S)
{
    __shared__ float tile[32][33];
    int p = blockIdx.z;
    int s0 = blockIdx.x * 32, r0 = blockIdx.y * 32;
    const float* ip = in + (size_t)p * R * S;
    __nv_bfloat16* op = out + (size_t)p * R * S;
    int tx = threadIdx.x, ty = threadIdx.y;
#pragma unroll
    for (int dy = 0; dy < 32; dy += 8) {
        int r = r0 + ty + dy, s = s0 + tx;
        tile[ty + dy][tx] = (r < R && s < S) ? ip[(size_t)r * S + s] : 0.f;
    }
    __syncthreads();
#pragma unroll
    for (int dy = 0; dy < 32; dy += 8) {
        int s = s0 + ty + dy, r = r0 + tx;
        if (s < S && r < R) op[(size_t)s * R + r] = __float2bfloat16(tile[tx][ty + dy]);
    }
}

__global__ void conv_w(const float* __restrict__ W, __nv_bfloat16* __restrict__ Wb)
{
    int i = blockIdx.x * 256 + threadIdx.x;
    if (i >= CH * CH) return;
    int o = i / CH, c = i % CH;
    Wb[i] = __float2bfloat16(W[(size_t)o * WCOLS + c]);
}

// ============================================================================
// bf16 tensor-core GEMM: Y[b][m][n] = sum_k A[m][woff..+k] * Bt[b][n][k]
// A = Wb row-major (ld CH), Bt = Xt (ld K). BM=BN=128, BK=32, 8 warps (2x4).
// ============================================================================
__global__ __launch_bounds__(256)
void level_mma(const __nv_bfloat16* __restrict__ Wb,
               const __nv_bfloat16* __restrict__ Xt,
               float* __restrict__ Y, int K, int Nloc, int woff)
{
    const int n0 = blockIdx.x * 128;
    const int m0 = blockIdx.y * 128;
    const int b  = blockIdx.z;

    __shared__ __align__(16) __nv_bfloat16 As[128][40];
    __shared__ __align__(16) __nv_bfloat16 Bs[128][40];

    const __nv_bfloat16* Xb = Xt + (size_t)b * Nloc * K;
    const int tid = threadIdx.x;
    const int lane = tid & 31, w = tid >> 5;
    const int wr = w >> 2, wc = w & 3;
    const int tg = lane & 3;

    float acc[4][4][4];
#pragma unroll
    for (int mi = 0; mi < 4; mi++)
#pragma unroll
        for (int ni = 0; ni < 4; ni++)
#pragma unroll
            for (int q = 0; q < 4; q++) acc[mi][ni][q] = 0.f;

    const int lr = tid >> 1;
    const int lv = tid & 1;

    // ldmatrix lane address components
    uint32_t asb = smem_u32(&As[0][0]);
    uint32_t bsb = smem_u32(&Bs[0][0]);
    uint32_t aAddr = asb + (((lane & 15) + wr * 64) * 40 + (lane >> 4) * 8) * 2;
    uint32_t bRow  = (lane & 7) + ((lane >> 4) & 1) * 8 + wc * 32;
    uint32_t bCol  = ((lane >> 3) & 1) * 8;
    uint32_t bAddr = bsb + (bRow * 40 + bCol) * 2;

    for (int k0 = 0; k0 < K; k0 += 32) {
        {
            const __nv_bfloat16* ap = &Wb[(size_t)(m0 + lr) * CH + woff + k0];
            uint4 va0 = *(const uint4*)(ap + lv * 8);
            uint4 va1 = *(const uint4*)(ap + (lv + 2) * 8);
            *(uint4*)&As[lr][lv * 8]       = va0;
            *(uint4*)&As[lr][(lv + 2) * 8] = va1;
            uint4 z = make_uint4(0, 0, 0, 0);
            uint4 vb0 = z, vb1 = z;
            int n = n0 + lr;
            if (n < Nloc) {
                const __nv_bfloat16* bp = &Xb[(size_t)n * K + k0];
                vb0 = *(const uint4*)(bp + lv * 8);
                vb1 = *(const uint4*)(bp + (lv + 2) * 8);
            }
            *(uint4*)&Bs[lr][lv * 8]       = vb0;
            *(uint4*)&Bs[lr][(lv + 2) * 8] = vb1;
        }
        __syncthreads();
#pragma unroll
        for (int ks = 0; ks < 32; ks += 16) {
            uint32_t bq[8];
            ldsm4(bq[0], bq[1], bq[2], bq[3], bAddr + ks * 2);
            ldsm4(bq[4], bq[5], bq[6], bq[7], bAddr + (16 * 40 + ks) * 2);
#pragma unroll
            for (int mi = 0; mi < 4; mi++) {
                uint32_t a0, a1, a2, a3;
                ldsm4(a0, a1, a2, a3, aAddr + (mi * 16 * 40 + ks) * 2);
#pragma unroll
                for (int ni = 0; ni < 4; ni++)
                    mma16816(acc[mi][ni], a0, a1, a2, a3, bq[ni * 2], bq[ni * 2 + 1]);
            }
        }
        __syncthreads();
    }

    float* Yb = Y + (size_t)b * CH * Nloc;
    const int g = lane >> 2;
#pragma unroll
    for (int mi = 0; mi < 4; mi++) {
        int r = m0 + wr * 64 + mi * 16 + g;
#pragma unroll
        for (int ni = 0; ni < 4; ni++) {
            int ccol = n0 + wc * 32 + ni * 8 + 2 * tg;
            if (ccol < Nloc) {
                *(float2*)&Yb[(size_t)r * Nloc + ccol] =
                    make_float2(acc[mi][ni][0], acc[mi][ni][1]);
                *(float2*)&Yb[(size_t)(r + 8) * Nloc + ccol] =
                    make_float2(acc[mi][ni][2], acc[mi][ni][3]);
            }
        }
    }
}

// ============================================================================
// 3x3 avg pool, stride 1, zero pad, /9, compile-time S
// ============================================================================
template<int S>
__global__ void pool3k(const float* __restrict__ in, float* __restrict__ out, int total)
{
    int idx = blockIdx.x * blockDim.x + threadIdx.x;
    if (idx >= total) return;
    int w = idx % S;
    int h = (idx / S) % S;
    const float* ip = in + (idx - h * S - w);
    float s;
    if (h > 0 && h < S - 1 && w > 0 && w < S - 1) {
        const float* p = ip + (h - 1) * S + (w - 1);
        s = p[0] + p[1] + p[2] + p[S] + p[S + 1] + p[S + 2]
          + p[2 * S] + p[2 * S + 1] + p[2 * S + 2];
    } else {
        s = 0.f;
#pragma unroll
        for (int dh = -1; dh <= 1; dh++) {
            int hh = h + dh;
            if (hh < 0 || hh >= S) continue;
#pragma unroll
            for (int dw = -1; dw <= 1; dw++) {
                int ww = w + dw;
                if (ww < 0 || ww >= S) continue;
                s += ip[hh * S + ww];
            }
        }
    }
    out[idx] = s * (1.f / 9.f);
}

__device__ __forceinline__ float bilin(const float* __restrict__ p, int S, int h, int w)
{
    float scale = (float)S / 56.f;
    float cy = (h + 0.5f) * scale - 0.5f;
    float cx = (w + 0.5f) * scale - 0.5f;
    float fy0 = floorf(cy), fx0 = floorf(cx);
    float fy = cy - fy0, fx = cx - fx0;
    int y0 = (int)fy0, x0 = (int)fx0;
    int y0c = max(y0, 0), y1c = min(y0 + 1, S - 1);
    int x0c = max(x0, 0), x1c = min(x0 + 1, S - 1);
    float v00 = p[y0c * S + x0c], v01 = p[y0c * S + x1c];
    float v10 = p[y1c * S + x0c], v11 = p[y1c * S + x1c];
    return (1.f - fy) * ((1.f - fx) * v00 + fx * v01)
         +        fy  * ((1.f - fx) * v10 + fx * v11);
}

__global__ void assemble(const float* __restrict__ Wmat, const float* __restrict__ bvec)
{
    int idx = blockIdx.x * blockDim.x + threadIdx.x;
    if (idx >= BATCH * CH * HW) return;
    int w = idx % 56;
    int h = (idx / 56) % 56;
    int o = (idx / HW) % CH;
    int b = idx / (HW * CH);

    float v = g_p1[idx];
    const float* p2 = g_p2 + ((size_t)(b * CH) + o) * 784;
    const float* p3 = g_p3 + ((size_t)(b * CH) + o) * 196;
    v += bilin(p2, 28, h, w);
    v += bilin(p3, 14, h, w);
    float xx = fmaf(2.f / 55.f, (float)w, -1.f);
    float yy = fmaf(2.f / 55.f, (float)h, -1.f);
    v += Wmat[(size_t)o * WCOLS + 1792] * xx
       + Wmat[(size_t)o * WCOLS + 1793] * yy
       + bvec[o];
    g_phi[idx] = v;
}

__global__ void row_norms()
{
    int i = blockIdx.x * blockDim.x + threadIdx.x;
    int b = blockIdx.y;
    if (i >= HW) return;
    const float* p = g_phi + (size_t)b * CH * HW + i;
    float s = 0.f;
#pragma unroll 4
    for (int k = 0; k < CH; k++) {
        float v = p[(size_t)k * HW];
        s = fmaf(v, v, s);
    }
    g_rown[b * HW + i] = s;
}

__global__ void col_norms(const float* __restrict__ Cmat)
{
    int j = blockIdx.x * blockDim.x + threadIdx.x;
    if (j >= HW) return;
    float s = 0.f;
#pragma unroll 4
    for (int k = 0; k < CH; k++) {
        float v = Cmat[(size_t)k * HW + j];
        s = fmaf(v, v, s);
    }
    g_coln[j] = s;
}

// ============================================================================
// Fused distance GEMM (tensor core) + running top-3 of dist^2.
// A = phiT[b] (i, k) bf16, B = Ct (j, k) bf16. BM=BN=128, BK=32.
// grid (25 i-tiles, 8 batch, 3 j-splits)
// ============================================================================
__global__ __launch_bounds__(256)
void dist_mma(const __nv_bfloat16* __restrict__ phiT,
              const __nv_bfloat16* __restrict__ Ct)
{
    const int m0 = blockIdx.x * 128;
    const int b  = blockIdx.y;
    const int js = blockIdx.z;
    const int jt0 = (js * 25) / 3;
    const int jt1 = ((js + 1) * 25) / 3;

    __shared__ __align__(16) __nv_bfloat16 As[128][40];
    __shared__ __align__(16) __nv_bfloat16 Bs[128][40];
    __shared__ float red[4][128][3];

    const __nv_bfloat16* Ab = phiT + (size_t)b * HW * CH;
    const int tid = threadIdx.x;
    const int lane = tid & 31, w = tid >> 5;
    const int wr = w >> 2, wc = w & 3;
    const int g = lane >> 2, tg = lane & 3;

    uint32_t asb = smem_u32(&As[0][0]);
    uint32_t bsb = smem_u32(&Bs[0][0]);
    uint32_t aAddr = asb + (((lane & 15) + wr * 64) * 40 + (lane >> 4) * 8) * 2;
    uint32_t bRow  = (lane & 7) + ((lane >> 4) & 1) * 8 + wc * 32;
    uint32_t bCol  = ((lane >> 3) & 1) * 8;
    uint32_t bAddr = bsb + (bRow * 40 + bCol) * 2;

    const int lr = tid >> 1;
    const int lv = tid & 1;

    float nr[4][2];
    float t0[4][2], t1[4][2], t2[4][2];
#pragma unroll
    for (int mi = 0; mi < 4; mi++)
#pragma unroll
        for (int hh = 0; hh < 2; hh++) {
            int r = m0 + wr * 64 + mi * 16 + g + hh * 8;
            nr[mi][hh] = (r < HW) ? g_rown[b * HW + r] : 0.f;
            t0[mi][hh] = INFINITY; t1[mi][hh] = INFINITY; t2[mi][hh] = INFINITY;
        }

    for (int jt = jt0; jt < jt1; jt++) {
        const int n0 = jt * 128;
        float acc[4][4][4];
#pragma unroll
        for (int mi = 0; mi < 4; mi++)
#pragma unroll
            for (int ni = 0; ni < 4; ni++)
#pragma unroll
                for (int q = 0; q < 4; q++) acc[mi][ni][q] = 0.f;

        for (int k0 = 0; k0 < CH; k0 += 32) {
            uint4 z = make_uint4(0, 0, 0, 0);
            uint4 va0 = z, va1 = z, vb0 = z, vb1 = z;
            int iA = m0 + lr;
            if (iA < HW) {
                const __nv_bfloat16* ap = &Ab[(size_t)iA * CH + k0];
                va0 = *(const uint4*)(ap + lv * 8);
                va1 = *(const uint4*)(ap + (lv + 2) * 8);
            }
            int jB = n0 + lr;
            if (jB < HW) {
                const __nv_bfloat16* bp = &Ct[(size_t)jB * CH + k0];
                vb0 = *(const uint4*)(bp + lv * 8);
                vb1 = *(const uint4*)(bp + (lv + 2) * 8);
            }
            *(uint4*)&As[lr][lv * 8]       = va0;
            *(uint4*)&As[lr][(lv + 2) * 8] = va1;
            *(uint4*)&Bs[lr][lv * 8]       = vb0;
            *(uint4*)&Bs[lr][(lv + 2) * 8] = vb1;
            __syncthreads();
#pragma unroll
            for (int ks = 0; ks < 32; ks += 16) {
                uint32_t bq[8];
                ldsm4(bq[0], bq[1], bq[2], bq[3], bAddr + ks * 2);
                ldsm4(bq[4], bq[5], bq[6], bq[7], bAddr + (16 * 40 + ks) * 2);
#pragma unroll
                for (int mi = 0; mi < 4; mi++) {
                    uint32_t a0, a1, a2, a3;
                    ldsm4(a0, a1, a2, a3, aAddr + (mi * 16 * 40 + ks) * 2);
#pragma unroll
                    for (int ni = 0; ni < 4; ni++)
                        mma16816(acc[mi][ni], a0, a1, a2, a3, bq[ni * 2], bq[ni * 2 + 1]);
                }
            }
            __syncthreads();
        }

        // epilogue: d^2 = nr + coln - 2*dot, insert into running top-3
#pragma unroll
        for (int ni = 0; ni < 4; ni++) {
            int col0 = n0 + wc * 32 + ni * 8 + 2 * tg;
            if (col0 < HW) {
                float mj0 = g_coln[col0];
                float mj1 = g_coln[col0 + 1];
#pragma unroll
                for (int mi = 0; mi < 4; mi++) {
#pragma unroll
                    for (int hh = 0; hh < 2; hh++) {
                        float base = nr[mi][hh];
                        float d0 = fmaf(-2.f, acc[mi][ni][hh * 2],     base + mj0);
                        float d1 = fmaf(-2.f, acc[mi][ni][hh * 2 + 1], base + mj1);
                        ins3(t0[mi][hh], t1[mi][hh], t2[mi][hh], d0);
                        ins3(t0[mi][hh], t1[mi][hh], t2[mi][hh], d1);
                    }
                }
            }
        }
    }

    // reduce across the 4 lanes (tg) sharing each row
#pragma unroll
    for (int msk = 1; msk < 4; msk <<= 1) {
#pragma unroll
        for (int mi = 0; mi < 4; mi++)
#pragma unroll
            for (int hh = 0; hh < 2; hh++) {
                float b0 = __shfl_xor_sync(0xffffffffu, t0[mi][hh], msk);
                float b1 = __shfl_xor_sync(0xffffffffu, t1[mi][hh], msk);
                float b2 = __shfl_xor_sync(0xffffffffu, t2[mi][hh], msk);
                ins3(t0[mi][hh], t1[mi][hh], t2[mi][hh], b0);
                ins3(t0[mi][hh], t1[mi][hh], t2[mi][hh], b1);
                ins3(t0[mi][hh], t1[mi][hh], t2[mi][hh], b2);
            }
    }
    if (tg == 0) {
#pragma unroll
        for (int mi = 0; mi < 4; mi++)
#pragma unroll
            for (int hh = 0; hh < 2; hh++) {
                int rl = wr * 64 + mi * 16 + g + hh * 8;
                red[wc][rl][0] = t0[mi][hh];
                red[wc][rl][1] = t1[mi][hh];
                red[wc][rl][2] = t2[mi][hh];
            }
    }
    __syncthreads();
    if (tid < 128) {
        int ig = m0 + tid;
        if (ig < HW) {
            float a0 = INFINITY, a1 = INFINITY, a2 = INFINITY;
#pragma unroll
            for (int wcx = 0; wcx < 4; wcx++) {
                ins3(a0, a1, a2, red[wcx][tid][0]);
                ins3(a0, a1, a2, red[wcx][tid][1]);
                ins3(a0, a1, a2, red[wcx][tid][2]);
            }
            size_t base = (((size_t)b * 3 + js) * HW + ig) * 3;
            g_top3[base + 0] = a0;
            g_top3[base + 1] = a1;
            g_top3[base + 2] = a2;
        }
    }
}

__global__ void finalize(float* __restrict__ out)
{
    int idx = blockIdx.x * blockDim.x + threadIdx.x;
    if (idx >= BATCH * HW) return;
    int b = idx / HW;
    int i = idx % HW;
    float t0 = INFINITY, t1 = INFINITY, t2 = INFINITY;
#pragma unroll
    for (int js = 0; js < 3; js++) {
        size_t base = (((size_t)b * 3 + js) * HW + i) * 3;
        ins3(t0, t1, t2, g_top3[base + 0]);
        ins3(t0, t1, t2, g_top3[base + 1]);
        ins3(t0, t1, t2, g_top3[base + 2]);
    }
    float d0 = sqrtf(fmaxf(t0, 0.f));
    float d1 = sqrtf(fmaxf(t1, 0.f));
    float d2 = sqrtf(fmaxf(t2, 0.f));
    float w0 = 1.f / (1.f + expf(d0 - d1) + expf(d0 - d2));
    out[idx] = w0 * d0;
}

// ============================================================================
extern "C" void kernel_launch(void* const* d_in, const int* in_sizes, int n_in,
                              void* d_out, int out_size)
{
    const float *p1 = nullptr, *p2 = nullptr, *p3 = nullptr;
    const float *W = nullptr, *bv = nullptr, *Cm = nullptr;
    for (int i = 0; i < n_in; i++) {
        switch (in_sizes[i]) {
            case 8 * 256 * 56 * 56:  p1 = (const float*)d_in[i]; break;
            case 8 * 512 * 28 * 28:  p2 = (const float*)d_in[i]; break;
            case 8 * 1024 * 14 * 14: p3 = (const float*)d_in[i]; break;
            case 1792 * 1794:        W  = (const float*)d_in[i]; break;
            case 1792:               bv = (const float*)d_in[i]; break;
            case 1792 * 3136:        Cm = (const float*)d_in[i]; break;
            default: break;
        }
    }

    void *y1, *pp1, *y2, *pp2, *y3, *pp3, *phi;
    void *wb, *x1t, *x2t, *x3t, *ct, *phit;
    cudaGetSymbolAddress(&y1,  g_y1);   cudaGetSymbolAddress(&pp1, g_p1);
    cudaGetSymbolAddress(&y2,  g_y2);   cudaGetSymbolAddress(&pp2, g_p2);
    cudaGetSymbolAddress(&y3,  g_y3);   cudaGetSymbolAddress(&pp3, g_p3);
    cudaGetSymbolAddress(&phi, g_phi);
    cudaGetSymbolAddress(&wb,  g_Wb);   cudaGetSymbolAddress(&x1t, g_x1t);
    cudaGetSymbolAddress(&x2t, g_x2t);  cudaGetSymbolAddress(&x3t, g_x3t);
    cudaGetSymbolAddress(&ct,  g_Ct);   cudaGetSymbolAddress(&phit, g_phiT);

    dim3 tb(32, 8);
    // stage bf16 operands
    conv_w<<<(CH * CH + 255) / 256, 256>>>(W, (__nv_bfloat16*)wb);
    transpose_conv<<<dim3(98, 8,  8), tb>>>(p1, (__nv_bfloat16*)x1t, 256,  3136);
    transpose_conv<<<dim3(25, 16, 8), tb>>>(p2, (__nv_bfloat16*)x2t, 512,  784);
    transpose_conv<<<dim3(7,  32, 8), tb>>>(p3, (__nv_bfloat16*)x3t, 1024, 196);
    transpose_conv<<<dim3(98, 56, 1), tb>>>(Cm, (__nv_bfloat16*)ct,  1792, 3136);

    // channel-mix at native resolution (tensor cores)
    level_mma<<<dim3(25, 14, 8), 256>>>((const __nv_bfloat16*)wb, (const __nv_bfloat16*)x1t,
                                        (float*)y1, 256, 3136, 0);
    level_mma<<<dim3(7, 14, 8), 256>>>((const __nv_bfloat16*)wb, (const __nv_bfloat16*)x2t,
                                       (float*)y2, 512, 784, 256);
    level_mma<<<dim3(2, 14, 8), 256>>>((const __nv_bfloat16*)wb, (const __nv_bfloat16*)x3t,
                                       (float*)y3, 1024, 196, 768);

    const int tot1 = BATCH * CH * 3136;
    const int tot2 = BATCH * CH * 784;
    const int tot3 = BATCH * CH * 196;
    pool3k<56><<<(tot1 + 255) / 256, 256>>>((const float*)y1, (float*)pp1, tot1);
    pool3k<28><<<(tot2 + 255) / 256, 256>>>((const float*)y2, (float*)pp2, tot2);
    pool3k<14><<<(tot3 + 255) / 256, 256>>>((const float*)y3, (float*)pp3, tot3);

    assemble<<<(tot1 + 255) / 256, 256>>>(W, bv);

    transpose_conv<<<dim3(98, 56, 8), tb>>>((const float*)phi, (__nv_bfloat16*)phit,
                                            1792, 3136);
    row_norms<<<dim3((HW + 255) / 256, BATCH), 256>>>();
    col_norms<<<(HW + 255) / 256, 256>>>(Cm);

    dist_mma<<<dim3(25, BATCH, 3), 256>>>((const __nv_bfloat16*)phit,
                                          (const __nv_bfloat16*)ct);

    finalize<<<(BATCH * HW + 255) / 256, 256>>>((float*)d_out);
}

// round 3
// speedup vs baseline: 4.2277x; 1.3187x over previous
#include <cuda_runtime.h>
#include <cuda_bf16.h>
#include <math.h>
#include <stdint.h>

#define BATCH 8
#define CH    1792
#define HW    3136
#define WCOLS 1794
#define KT64  28      // CH / 64

// ---------------- scratch (device globals; no allocation APIs) ----------------
__device__ __nv_bfloat16 g_Wb [CH * CH];             // W[o][c] bf16
__device__ __nv_bfloat16 g_x1t[BATCH * 3136 * 256];  // (b, s, c)
__device__ __nv_bfloat16 g_x2t[BATCH * 784  * 512];
__device__ __nv_bfloat16 g_x3t[BATCH * 196  * 1024];
__device__ __nv_bfloat16 g_Ct [HW * CH];             // (j, k)
__device__ __nv_bfloat16 g_y1 [BATCH * CH * 3136];   // level GEMM out (b, o, s)
__device__ __nv_bfloat16 g_y2 [BATCH * CH * 784];
__device__ __nv_bfloat16 g_y3 [BATCH * CH * 196];
__device__ __nv_bfloat16 g_q1 [BATCH * CH * 3136];   // pooled
__device__ __nv_bfloat16 g_q2 [BATCH * CH * 784];
__device__ __nv_bfloat16 g_q3 [BATCH * CH * 196];
__device__ __nv_bfloat16 g_phiT[BATCH * HW * CH];    // (b, i, k)
__device__ float g_rownp[KT64][BATCH * HW];          // row-norm partials
__device__ float g_rown[BATCH * HW];
__device__ float g_coln[HW];
__device__ float g_top3[BATCH * 3 * HW * 3];

__device__ __forceinline__ void ins3(float &a0, float &a1, float &a2, float x)
{
    float o0 = fminf(a0, x);
    float o1 = fminf(a1, fmaxf(a0, x));
    float o2 = fminf(a2, fmaxf(a1, x));
    a0 = o0; a1 = o1; a2 = o2;
}

__device__ __forceinline__ uint32_t smem_u32(const void* p)
{
    uint32_t a;
    asm("{ .reg .u64 t; cvta.to.shared.u64 t, %1; cvt.u32.u64 %0, t; }"
        : "=r"(a) : "l"(p));
    return a;
}

__device__ __forceinline__ void ldsm4(uint32_t &r0, uint32_t &r1, uint32_t &r2,
                                      uint32_t &r3, uint32_t addr)
{
    asm volatile("ldmatrix.sync.aligned.m8n8.x4.shared.b16 {%0,%1,%2,%3}, [%4];"
                 : "=r"(r0), "=r"(r1), "=r"(r2), "=r"(r3) : "r"(addr));
}

__device__ __forceinline__ void mma16816(float c[4],
                                         uint32_t a0, uint32_t a1, uint32_t a2, uint32_t a3,
                                         uint32_t b0, uint32_t b1)
{
    asm volatile("mma.sync.aligned.m16n8k16.row.col.f32.bf16.bf16.f32 "
                 "{%0,%1,%2,%3}, {%4,%5,%6,%7}, {%8,%9}, {%0,%1,%2,%3};"
                 : "+f"(c[0]), "+f"(c[1]), "+f"(c[2]), "+f"(c[3])
                 : "r"(a0), "r"(a1), "r"(a2), "r"(a3), "r"(b0), "r"(b1));
}

__device__ __forceinline__ void cpa16(uint32_t dst, const void* src, int srcBytes)
{
    asm volatile("cp.async.cg.shared.global [%0], [%1], 16, %2;"
                 :: "r"(dst), "l"(src), "r"(srcBytes));
}
__device__ __forceinline__ void cpa_commit()
{
    asm volatile("cp.async.commit_group;");
}
template<int N> __device__ __forceinline__ void cpa_wait()
{
    asm volatile("cp.async.wait_group %0;" :: "n"(N));
}

// ============================================================================
// fp32 (P, R, S) -> bf16 (P, S, R) tiled transpose+convert
// ============================================================================
__global__ void transpose_conv(const float* __restrict__ in,
                               __nv_bfloat16* __restrict__ out, int R, int S)
{
    __shared__ float tile[32][33];
    int p = blockIdx.z;
    int s0 = blockIdx.x * 32, r0 = blockIdx.y * 32;
    const float* ip = in + (size_t)p * R * S;
    __nv_bfloat16* op = out + (size_t)p * R * S;
    int tx = threadIdx.x, ty = threadIdx.y;
#pragma unroll
    for (int dy = 0; dy < 32; dy += 8) {
        int r = r0 + ty + dy, s = s0 + tx;
        tile[ty + dy][tx] = (r < R && s < S) ? ip[(size_t)r * S + s] : 0.f;
    }
    __syncthreads();
#pragma unroll
    for (int dy = 0; dy < 32; dy += 8) {
        int s = s0 + ty + dy, r = r0 + tx;
        if (s < S && r < R) op[(size_t)s * R + r] = __float2bfloat16(tile[tx][ty + dy]);
    }
}

__global__ void conv_w(const float* __restrict__ W, __nv_bfloat16* __restrict__ Wb)
{
    int i = blockIdx.x * 256 + threadIdx.x;
    if (i >= CH * CH) return;
    int o = i / CH, c = i % CH;
    Wb[i] = __float2bfloat16(W[(size_t)o * WCOLS + c]);
}

// ============================================================================
// bf16 MMA GEMM, cp.async double-buffered: Y[b][m][n] = sum_k Wb[m][woff+k]*Xt[b][n][k]
// BM=BN=128, BK=32, 256 threads, bf16 output.
// ============================================================================
__global__ __launch_bounds__(256)
void level_mma(const __nv_bfloat16* __restrict__ Xt,
               __nv_bfloat16* __restrict__ Y, int K, int Nloc, int woff)
{
    const int n0 = blockIdx.x * 128;
    const int m0 = blockIdx.y * 128;
    const int b  = blockIdx.z;

    __shared__ __align__(16) __nv_bfloat16 As[2][128][40];
    __shared__ __align__(16) __nv_bfloat16 Bs[2][128][40];
    const uint32_t STG = 128 * 40 * 2;

    const __nv_bfloat16* Xb = Xt + (size_t)b * Nloc * K;
    const int tid = threadIdx.x;
    const int lane = tid & 31, w = tid >> 5;
    const int wr = w >> 2, wc = w & 3;
    const int tg = lane & 3, g = lane >> 2;

    float acc[4][4][4];
#pragma unroll
    for (int mi = 0; mi < 4; mi++)
#pragma unroll
        for (int ni = 0; ni < 4; ni++)
#pragma unroll
            for (int q = 0; q < 4; q++) acc[mi][ni][q] = 0.f;

    const int lr = tid >> 1, lv = tid & 1;
    uint32_t asb = smem_u32(&As[0][0][0]);
    uint32_t bsb = smem_u32(&Bs[0][0][0]);
    uint32_t aAddr = asb + (((lane & 15) + wr * 64) * 40 + (lane >> 4) * 8) * 2;
    uint32_t bRow  = (lane & 7) + ((lane >> 4) & 1) * 8 + wc * 32;
    uint32_t bAddr = bsb + (bRow * 40 + ((lane >> 3) & 1) * 8) * 2;
    uint32_t aWr = asb + (lr * 40 + lv * 8) * 2;
    uint32_t bWr = bsb + (lr * 40 + lv * 8) * 2;

    const __nv_bfloat16* apB = g_Wb + (size_t)(m0 + lr) * CH + woff + lv * 8;
    int jB = n0 + lr;
    const __nv_bfloat16* bpB = Xb + (size_t)(jB < Nloc ? jB : Nloc - 1) * K + lv * 8;
    const int bvld = (jB < Nloc) ? 16 : 0;

    const int KT = K / 32;
    // prologue: stage 0
    cpa16(aWr, apB, 16);            cpa16(aWr + 32, apB + 16, 16);
    cpa16(bWr, bpB, bvld);          cpa16(bWr + 32, bpB + 16, bvld);
    cpa_commit();

    for (int kt = 0; kt < KT; kt++) {
        const int st = kt & 1;
        if (kt + 1 < KT) {
            const int so = (kt + 1) & 1;
            const int k0 = (kt + 1) * 32;
            cpa16(aWr + so * STG, apB + k0, 16);
            cpa16(aWr + so * STG + 32, apB + k0 + 16, 16);
            cpa16(bWr + so * STG, bpB + k0, bvld);
            cpa16(bWr + so * STG + 32, bpB + k0 + 16, bvld);
            cpa_commit();
            cpa_wait<1>();
        } else {
            cpa_wait<0>();
        }
        __syncthreads();
#pragma unroll
        for (int ks = 0; ks < 32; ks += 16) {
            uint32_t bq[8];
            ldsm4(bq[0], bq[1], bq[2], bq[3], bAddr + st * STG + ks * 2);
            ldsm4(bq[4], bq[5], bq[6], bq[7], bAddr + st * STG + (16 * 40 + ks) * 2);
#pragma unroll
            for (int mi = 0; mi < 4; mi++) {
                uint32_t a0, a1, a2, a3;
                ldsm4(a0, a1, a2, a3, aAddr + st * STG + (mi * 16 * 40 + ks) * 2);
#pragma unroll
                for (int ni = 0; ni < 4; ni++)
                    mma16816(acc[mi][ni], a0, a1, a2, a3, bq[ni * 2], bq[ni * 2 + 1]);
            }
        }
        __syncthreads();
    }

    __nv_bfloat16* Yb = Y + (size_t)b * CH * Nloc;
#pragma unroll
    for (int mi = 0; mi < 4; mi++) {
        int r = m0 + wr * 64 + mi * 16 + g;
#pragma unroll
        for (int ni = 0; ni < 4; ni++) {
            int ccol = n0 + wc * 32 + ni * 8 + 2 * tg;
            if (ccol < Nloc) {
                *reinterpret_cast<__nv_bfloat162*>(&Yb[(size_t)r * Nloc + ccol]) =
                    __floats2bfloat162_rn(acc[mi][ni][0], acc[mi][ni][1]);
                *reinterpret_cast<__nv_bfloat162*>(&Yb[(size_t)(r + 8) * Nloc + ccol]) =
                    __floats2bfloat162_rn(acc[mi][ni][2], acc[mi][ni][3]);
            }
        }
    }
}

// ============================================================================
// 3x3 avg pool (zero pad, /9), bf16 in/out, fp32 accum
// ============================================================================
template<int S>
__global__ void pool3b(const __nv_bfloat16* __restrict__ in,
                       __nv_bfloat16* __restrict__ out, int total)
{
    int idx = blockIdx.x * blockDim.x + threadIdx.x;
    if (idx >= total) return;
    int w = idx % S;
    int h = (idx / S) % S;
    const __nv_bfloat16* ip = in + (idx - h * S - w);
    float s;
    if (h > 0 && h < S - 1 && w > 0 && w < S - 1) {
        const __nv_bfloat16* p = ip + (h - 1) * S + (w - 1);
        s = __bfloat162float(p[0]) + __bfloat162float(p[1]) + __bfloat162float(p[2])
          + __bfloat162float(p[S]) + __bfloat162float(p[S + 1]) + __bfloat162float(p[S + 2])
          + __bfloat162float(p[2*S]) + __bfloat162float(p[2*S + 1]) + __bfloat162float(p[2*S + 2]);
    } else {
        s = 0.f;
#pragma unroll
        for (int dh = -1; dh <= 1; dh++) {
            int hh = h + dh;
            if (hh < 0 || hh >= S) continue;
#pragma unroll
            for (int dw = -1; dw <= 1; dw++) {
                int ww = w + dw;
                if (ww < 0 || ww >= S) continue;
                s += __bfloat162float(ip[hh * S + ww]);
            }
        }
    }
    out[idx] = __float2bfloat16(s * (1.f / 9.f));
}

// ============================================================================
// Fused assemble: phi = q1 + up2(q2) + up4(q3) + coord/bias terms,
// writes bf16 phiT (b, i, k) directly + row-norm partials. Tile (k=64, i=64).
// ============================================================================
__global__ __launch_bounds__(256)
void assemble_t(const float* __restrict__ Wmat, const float* __restrict__ bvec)
{
    __shared__ float tile[64][65];
    __shared__ float rsum[4][64];
    const int i0 = blockIdx.x * 64;
    const int kt = blockIdx.y;
    const int k0 = kt * 64;
    const int b  = blockIdx.z;
    const int tx = threadIdx.x;   // 0..63 (i)
    const int ty = threadIdx.y;   // 0..3
    const int i  = i0 + tx;
    const int h = i / 56, w = i % 56;

    float w2[4]; int o2[4];
    {
        float cy = (h + 0.5f) * 0.5f - 0.5f;
        float cx = (w + 0.5f) * 0.5f - 0.5f;
        float fy0 = floorf(cy), fx0 = floorf(cx);
        float fy = cy - fy0, fx = cx - fx0;
        int y0 = max((int)fy0, 0), y1 = min((int)fy0 + 1, 27);
        int x0 = max((int)fx0, 0), x1 = min((int)fx0 + 1, 27);
        o2[0] = y0 * 28 + x0; o2[1] = y0 * 28 + x1;
        o2[2] = y1 * 28 + x0; o2[3] = y1 * 28 + x1;
        w2[0] = (1.f - fy) * (1.f - fx); w2[1] = (1.f - fy) * fx;
        w2[2] = fy * (1.f - fx);         w2[3] = fy * fx;
    }
    float w3[4]; int o3[4];
    {
        float cy = (h + 0.5f) * 0.25f - 0.5f;
        float cx = (w + 0.5f) * 0.25f - 0.5f;
        float fy0 = floorf(cy), fx0 = floorf(cx);
        float fy = cy - fy0, fx = cx - fx0;
        int y0 = max((int)fy0, 0), y1 = min((int)fy0 + 1, 13);
        int x0 = max((int)fx0, 0), x1 = min((int)fx0 + 1, 13);
        o3[0] = y0 * 14 + x0; o3[1] = y0 * 14 + x1;
        o3[2] = y1 * 14 + x0; o3[3] = y1 * 14 + x1;
        w3[0] = (1.f - fy) * (1.f - fx); w3[1] = (1.f - fy) * fx;
        w3[2] = fy * (1.f - fx);         w3[3] = fy * fx;
    }
    const float xx = fmaf(2.f / 55.f, (float)w, -1.f);
    const float yy = fmaf(2.f / 55.f, (float)h, -1.f);

    float s = 0.f;
    for (int r = ty; r < 64; r += 4) {
        const int k = k0 + r;
        const size_t pk = (size_t)b * CH + k;
        float v = __bfloat162float(g_q1[pk * 3136 + i]);
        const __nv_bfloat16* pl2 = g_q2 + pk * 784;
        const __nv_bfloat16* pl3 = g_q3 + pk * 196;
        v += w2[0] * __bfloat162float(pl2[o2[0]]) + w2[1] * __bfloat162float(pl2[o2[1]])
           + w2[2] * __bfloat162float(pl2[o2[2]]) + w2[3] * __bfloat162float(pl2[o2[3]]);
        v += w3[0] * __bfloat162float(pl3[o3[0]]) + w3[1] * __bfloat162float(pl3[o3[1]])
           + w3[2] * __bfloat162float(pl3[o3[2]]) + w3[3] * __bfloat162float(pl3[o3[3]]);
        v += Wmat[(size_t)k * WCOLS + 1792] * xx
           + Wmat[(size_t)k * WCOLS + 1793] * yy
           + bvec[k];
        float fq = __bfloat162float(__float2bfloat16(v)); // dequantized (GEMM-consistent)
        tile[r][tx] = fq;
        s = fmaf(fq, fq, s);
    }
    rsum[ty][tx] = s;
    __syncthreads();
    if (ty == 0)
        g_rownp[kt][b * HW + i] = rsum[0][tx] + rsum[1][tx] + rsum[2][tx] + rsum[3][tx];
#pragma unroll
    for (int q = 0; q < 16; q++) {
        int ri = ty + q * 4;
        g_phiT[((size_t)b * HW + (i0 + ri)) * CH + k0 + tx] =
            __float2bfloat16(tile[tx][ri]);
    }
}

__global__ void reduce_rown()
{
    int idx = blockIdx.x * 256 + threadIdx.x;
    if (idx >= BATCH * HW) return;
    float s = 0.f;
#pragma unroll
    for (int q = 0; q < KT64; q++) s += g_rownp[q][idx];
    g_rown[idx] = s;
}

__global__ void col_norms_b()
{
    int gw = (blockIdx.x * 256 + threadIdx.x) >> 5;
    int lane = threadIdx.x & 31;
    if (gw >= HW) return;
    const __nv_bfloat16* row = g_Ct + (size_t)gw * CH;
    float s = 0.f;
    for (int k = lane; k < CH; k += 32) {
        float v = __bfloat162float(row[k]);
        s = fmaf(v, v, s);
    }
#pragma unroll
    for (int m = 16; m; m >>= 1) s += __shfl_xor_sync(0xffffffffu, s, m);
    if (lane == 0) g_coln[gw] = s;
}

// ============================================================================
// Fused distance GEMM (cp.async pipelined) + running top-3 of dist^2
// ============================================================================
__global__ __launch_bounds__(256)
void dist_mma()
{
    const int m0 = blockIdx.x * 128;
    const int b  = blockIdx.y;
    const int js = blockIdx.z;
    const int jt0 = (js * 25) / 3;
    const int jt1 = ((js + 1) * 25) / 3;

    __shared__ __align__(16) __nv_bfloat16 As[2][128][40];
    __shared__ __align__(16) __nv_bfloat16 Bs[2][128][40];
    __shared__ float red[4][128][3];
    const uint32_t STG = 128 * 40 * 2;

    const __nv_bfloat16* Ab = g_phiT + (size_t)b * HW * CH;
    const int tid = threadIdx.x;
    const int lane = tid & 31, w = tid >> 5;
    const int wr = w >> 2, wc = w & 3;
    const int g = lane >> 2, tg = lane & 3;

    uint32_t asb = smem_u32(&As[0][0][0]);
    uint32_t bsb = smem_u32(&Bs[0][0][0]);
    uint32_t aAddr = asb + (((lane & 15) + wr * 64) * 40 + (lane >> 4) * 8) * 2;
    uint32_t bRow  = (lane & 7) + ((lane >> 4) & 1) * 8 + wc * 32;
    uint32_t bAddr = bsb + (bRow * 40 + ((lane >> 3) & 1) * 8) * 2;

    const int lr = tid >> 1, lv = tid & 1;
    uint32_t aWr = asb + (lr * 40 + lv * 8) * 2;
    uint32_t bWr = bsb + (lr * 40 + lv * 8) * 2;

    const int iA = m0 + lr;
    const __nv_bfloat16* apB = Ab + (size_t)(iA < HW ? iA : HW - 1) * CH + lv * 8;
    const int avld = (iA < HW) ? 16 : 0;

    float nr[4][2];
    float t0[4][2], t1[4][2], t2[4][2];
#pragma unroll
    for (int mi = 0; mi < 4; mi++)
#pragma unroll
        for (int hh = 0; hh < 2; hh++) {
            int r = m0 + wr * 64 + mi * 16 + g + hh * 8;
            nr[mi][hh] = (r < HW) ? g_rown[b * HW + r] : 0.f;
            t0[mi][hh] = INFINITY; t1[mi][hh] = INFINITY; t2[mi][hh] = INFINITY;
        }

    for (int jt = jt0; jt < jt1; jt++) {
        const int n0 = jt * 128;
        const int jB = n0 + lr;
        const __nv_bfloat16* bpB = g_Ct + (size_t)(jB < HW ? jB : HW - 1) * CH + lv * 8;
        const int bvld = (jB < HW) ? 16 : 0;

        float acc[4][4][4];
#pragma unroll
        for (int mi = 0; mi < 4; mi++)
#pragma unroll
            for (int ni = 0; ni < 4; ni++)
#pragma unroll
                for (int q = 0; q < 4; q++) acc[mi][ni][q] = 0.f;

        // prologue: stage 0
        cpa16(aWr, apB, avld);          cpa16(aWr + 32, apB + 16, avld);
        cpa16(bWr, bpB, bvld);          cpa16(bWr + 32, bpB + 16, bvld);
        cpa_commit();

        for (int kt = 0; kt < CH / 32; kt++) {
            const int st = kt & 1;
            if (kt + 1 < CH / 32) {
                const int so = (kt + 1) & 1;
                const int k0 = (kt + 1) * 32;
                cpa16(aWr + so * STG, apB + k0, avld);
                cpa16(aWr + so * STG + 32, apB + k0 + 16, avld);
                cpa16(bWr + so * STG, bpB + k0, bvld);
                cpa16(bWr + so * STG + 32, bpB + k0 + 16, bvld);
                cpa_commit();
                cpa_wait<1>();
            } else {
                cpa_wait<0>();
            }
            __syncthreads();
#pragma unroll
            for (int ks = 0; ks < 32; ks += 16) {
                uint32_t bq[8];
                ldsm4(bq[0], bq[1], bq[2], bq[3], bAddr + st * STG + ks * 2);
                ldsm4(bq[4], bq[5], bq[6], bq[7], bAddr + st * STG + (16 * 40 + ks) * 2);
#pragma unroll
                for (int mi = 0; mi < 4; mi++) {
                    uint32_t a0, a1, a2, a3;
                    ldsm4(a0, a1, a2, a3, aAddr + st * STG + (mi * 16 * 40 + ks) * 2);
#pragma unroll
                    for (int ni = 0; ni < 4; ni++)
                        mma16816(acc[mi][ni], a0, a1, a2, a3, bq[ni * 2], bq[ni * 2 + 1]);
                }
            }
            __syncthreads();
        }

        // epilogue: d^2 = nr + coln - 2*dot -> running top-3
#pragma unroll
        for (int ni = 0; ni < 4; ni++) {
            int col0 = n0 + wc * 32 + ni * 8 + 2 * tg;
            if (col0 < HW) {
                float mj0 = g_coln[col0];
                float mj1 = g_coln[col0 + 1];
#pragma unroll
                for (int mi = 0; mi < 4; mi++) {
#pragma unroll
                    for (int hh = 0; hh < 2; hh++) {
                        float base = nr[mi][hh];
                        float d0 = fmaf(-2.f, acc[mi][ni][hh * 2],     base + mj0);
                        float d1 = fmaf(-2.f, acc[mi][ni][hh * 2 + 1], base + mj1);
                        ins3(t0[mi][hh], t1[mi][hh], t2[mi][hh], d0);
                        ins3(t0[mi][hh], t1[mi][hh], t2[mi][hh], d1);
                    }
                }
            }
        }
    }

    // reduce across the 4 lanes (tg) sharing each row
#pragma unroll
    for (int msk = 1; msk < 4; msk <<= 1) {
#pragma unroll
        for (int mi = 0; mi < 4; mi++)
#pragma unroll
            for (int hh = 0; hh < 2; hh++) {
                float b0 = __shfl_xor_sync(0xffffffffu, t0[mi][hh], msk);
                float b1 = __shfl_xor_sync(0xffffffffu, t1[mi][hh], msk);
                float b2 = __shfl_xor_sync(0xffffffffu, t2[mi][hh], msk);
                ins3(t0[mi][hh], t1[mi][hh], t2[mi][hh], b0);
                ins3(t0[mi][hh], t1[mi][hh], t2[mi][hh], b1);
                ins3(t0[mi][hh], t1[mi][hh], t2[mi][hh], b2);
            }
    }
    if (tg == 0) {
#pragma unroll
        for (int mi = 0; mi < 4; mi++)
#pragma unroll
            for (int hh = 0; hh < 2; hh++) {
                int rl = wr * 64 + mi * 16 + g + hh * 8;
                red[wc][rl][0] = t0[mi][hh];
                red[wc][rl][1] = t1[mi][hh];
                red[wc][rl][2] = t2[mi][hh];
            }
    }
    __syncthreads();
    if (tid < 128) {
        int ig = m0 + tid;
        if (ig < HW) {
            float a0 = INFINITY, a1 = INFINITY, a2 = INFINITY;
#pragma unroll
            for (int wcx = 0; wcx < 4; wcx++) {
                ins3(a0, a1, a2, red[wcx][tid][0]);
                ins3(a0, a1, a2, red[wcx][tid][1]);
                ins3(a0, a1, a2, red[wcx][tid][2]);
            }
            size_t base = (((size_t)b * 3 + js) * HW + ig) * 3;
            g_top3[base + 0] = a0;
            g_top3[base + 1] = a1;
            g_top3[base + 2] = a2;
        }
    }
}

__global__ void finalize(float* __restrict__ out)
{
    int idx = blockIdx.x * blockDim.x + threadIdx.x;
    if (idx >= BATCH * HW) return;
    int b = idx / HW;
    int i = idx % HW;
    float t0 = INFINITY, t1 = INFINITY, t2 = INFINITY;
#pragma unroll
    for (int js = 0; js < 3; js++) {
        size_t base = (((size_t)b * 3 + js) * HW + i) * 3;
        ins3(t0, t1, t2, g_top3[base + 0]);
        ins3(t0, t1, t2, g_top3[base + 1]);
        ins3(t0, t1, t2, g_top3[base + 2]);
    }
    float d0 = sqrtf(fmaxf(t0, 0.f));
    float d1 = sqrtf(fmaxf(t1, 0.f));
    float d2 = sqrtf(fmaxf(t2, 0.f));
    float w0 = 1.f / (1.f + expf(d0 - d1) + expf(d0 - d2));
    out[idx] = w0 * d0;
}

// ============================================================================
extern "C" void kernel_launch(void* const* d_in, const int* in_sizes, int n_in,
                              void* d_out, int out_size)
{
    const float *p1 = nullptr, *p2 = nullptr, *p3 = nullptr;
    const float *W = nullptr, *bv = nullptr, *Cm = nullptr;
    for (int i = 0; i < n_in; i++) {
        switch (in_sizes[i]) {
            case 8 * 256 * 56 * 56:  p1 = (const float*)d_in[i]; break;
            case 8 * 512 * 28 * 28:  p2 = (const float*)d_in[i]; break;
            case 8 * 1024 * 14 * 14: p3 = (const float*)d_in[i]; break;
            case 1792 * 1794:        W  = (const float*)d_in[i]; break;
            case 1792:               bv = (const float*)d_in[i]; break;
            case 1792 * 3136:        Cm = (const float*)d_in[i]; break;
            default: break;
        }
    }

    void *wb, *x1t, *x2t, *x3t, *ct;
    void *y1, *y2, *y3, *q1, *q2, *q3;
    cudaGetSymbolAddress(&wb,  g_Wb);
    cudaGetSymbolAddress(&x1t, g_x1t);
    cudaGetSymbolAddress(&x2t, g_x2t);
    cudaGetSymbolAddress(&x3t, g_x3t);
    cudaGetSymbolAddress(&ct,  g_Ct);
    cudaGetSymbolAddress(&y1,  g_y1);  cudaGetSymbolAddress(&q1, g_q1);
    cudaGetSymbolAddress(&y2,  g_y2);  cudaGetSymbolAddress(&q2, g_q2);
    cudaGetSymbolAddress(&y3,  g_y3);  cudaGetSymbolAddress(&q3, g_q3);

    dim3 tb(32, 8);
    conv_w<<<(CH * CH + 255) / 256, 256>>>(W, (__nv_bfloat16*)wb);
    transpose_conv<<<dim3(98, 8,  8), tb>>>(p1, (__nv_bfloat16*)x1t, 256,  3136);
    transpose_conv<<<dim3(25, 16, 8), tb>>>(p2, (__nv_bfloat16*)x2t, 512,  784);
    transpose_conv<<<dim3(7,  32, 8), tb>>>(p3, (__nv_bfloat16*)x3t, 1024, 196);
    transpose_conv<<<dim3(98, 56, 1), tb>>>(Cm, (__nv_bfloat16*)ct,  1792, 3136);

    level_mma<<<dim3(25, 14, 8), 256>>>((const __nv_bfloat16*)x1t,
                                        (__nv_bfloat16*)y1, 256, 3136, 0);
    level_mma<<<dim3(7, 14, 8), 256>>>((const __nv_bfloat16*)x2t,
                                       (__nv_bfloat16*)y2, 512, 784, 256);
    level_mma<<<dim3(2, 14, 8), 256>>>((const __nv_bfloat16*)x3t,
                                       (__nv_bfloat16*)y3, 1024, 196, 768);

    const int tot1 = BATCH * CH * 3136;
    const int tot2 = BATCH * CH * 784;
    const int tot3 = BATCH * CH * 196;
    pool3b<56><<<(tot1 + 255) / 256, 256>>>((const __nv_bfloat16*)y1,
                                            (__nv_bfloat16*)q1, tot1);
    pool3b<28><<<(tot2 + 255) / 256, 256>>>((const __nv_bfloat16*)y2,
                                            (__nv_bfloat16*)q2, tot2);
    pool3b<14><<<(tot3 + 255) / 256, 256>>>((const __nv_bfloat16*)y3,
                                            (__nv_bfloat16*)q3, tot3);

    assemble_t<<<dim3(49, 28, 8), dim3(64, 4)>>>(W, bv);
    reduce_rown<<<(BATCH * HW + 255) / 256, 256>>>();
    col_norms_b<<<(HW * 32 + 255) / 256, 256>>>();

    dist_mma<<<dim3(25, BATCH, 3), 256>>>();

    finalize<<<(BATCH * HW + 255) / 256, 256>>>((float*)d_out);
}